// round 15
// baseline (speedup 1.0000x reference)
#include <cuda_runtime.h>
#include <cuda_fp16.h>
#include <cstdint>

#define NH    32
#define NKVH  8
#define HD    128
#define BK    64
#define BQ    64
#define NTHR  128
#define MAXBLK 64

// ---- static device scratch (no allocations) ----
__device__ __half g_k[(size_t)MAXBLK * NKVH * BK * HD];
__device__ __half g_v[(size_t)MAXBLK * NKVH * BK * HD];

// ---- helpers ----
__device__ __forceinline__ uint32_t smem_u32(const void* p) {
    uint32_t a;
    asm("{ .reg .u64 t; cvta.to.shared.u64 t, %1; cvt.u32.u64 %0, t; }" : "=r"(a) : "l"(p));
    return a;
}
__device__ __forceinline__ void cp16(uint32_t dst, const void* src) {
    asm volatile("cp.async.cg.shared.global [%0], [%1], 16;" :: "r"(dst), "l"(src) : "memory");
}
#define CP_COMMIT() asm volatile("cp.async.commit_group;" ::: "memory")
#define CP_WAIT0()  asm volatile("cp.async.wait_group 0;" ::: "memory")
#define CP_WAIT1()  asm volatile("cp.async.wait_group 1;" ::: "memory")

__device__ __forceinline__ void ldsm4(uint32_t addr, uint32_t* r) {
    asm volatile("ldmatrix.sync.aligned.m8n8.x4.shared.b16 {%0,%1,%2,%3}, [%4];"
        : "=r"(r[0]), "=r"(r[1]), "=r"(r[2]), "=r"(r[3]) : "r"(addr));
}
__device__ __forceinline__ void ldsm4t(uint32_t addr, uint32_t* r) {
    asm volatile("ldmatrix.sync.aligned.m8n8.x4.trans.shared.b16 {%0,%1,%2,%3}, [%4];"
        : "=r"(r[0]), "=r"(r[1]), "=r"(r[2]), "=r"(r[3]) : "r"(addr));
}
__device__ __forceinline__ void mma_f16(float* c, const uint32_t* a, const uint32_t* b) {
    asm volatile("mma.sync.aligned.m16n8k16.row.col.f32.f16.f16.f32 "
        "{%0,%1,%2,%3}, {%4,%5,%6,%7}, {%8,%9}, {%0,%1,%2,%3};"
        : "+f"(c[0]), "+f"(c[1]), "+f"(c[2]), "+f"(c[3])
        : "r"(a[0]), "r"(a[1]), "r"(a[2]), "r"(a[3]), "r"(b[0]), "r"(b[1]));
}
// swizzled byte offset inside a tile with 256B rows (16 x 16B chunks)
__device__ __forceinline__ uint32_t swz(int row, int cb) {
    return (uint32_t)(row * 256 + ((cb ^ (row & 7)) << 4));
}

// ---- prep kernel: gather-convert K,V to [blk*kvh][key][d] fp16 ----
__global__ __launch_bounds__(256) void prep_kv(const float* __restrict__ kc,
                                               const float* __restrict__ vc) {
    int bb = blockIdx.x;            // 0..1023
    int b = bb >> 1, half = bb & 1;
    int blk = b >> 3, kvh = b & 7;
    #pragma unroll
    for (int j = 0; j < 2; ++j) {
        int c = threadIdx.x + j * 256 + half * 512;
        int row = c >> 4, d = (c & 15) * 8;
        const size_t src = ((size_t)(blk * BK + row) * NKVH + kvh) * HD + d;
        const size_t dst = ((size_t)b * BK + row) * HD + d;
        float4 ka = *reinterpret_cast<const float4*>(kc + src);
        float4 kb = *reinterpret_cast<const float4*>(kc + src + 4);
        float4 va = *reinterpret_cast<const float4*>(vc + src);
        float4 vb = *reinterpret_cast<const float4*>(vc + src + 4);
        uint4 uk, uv;
        __half2 h;
        h = __floats2half2_rn(ka.x, ka.y); uk.x = *reinterpret_cast<uint32_t*>(&h);
        h = __floats2half2_rn(ka.z, ka.w); uk.y = *reinterpret_cast<uint32_t*>(&h);
        h = __floats2half2_rn(kb.x, kb.y); uk.z = *reinterpret_cast<uint32_t*>(&h);
        h = __floats2half2_rn(kb.z, kb.w); uk.w = *reinterpret_cast<uint32_t*>(&h);
        h = __floats2half2_rn(va.x, va.y); uv.x = *reinterpret_cast<uint32_t*>(&h);
        h = __floats2half2_rn(va.z, va.w); uv.y = *reinterpret_cast<uint32_t*>(&h);
        h = __floats2half2_rn(vb.x, vb.y); uv.z = *reinterpret_cast<uint32_t*>(&h);
        h = __floats2half2_rn(vb.z, vb.w); uv.w = *reinterpret_cast<uint32_t*>(&h);
        *reinterpret_cast<uint4*>(g_k + dst) = uk;
        *reinterpret_cast<uint4*>(g_v + dst) = uv;
    }
}

// ---- main kernel ----
// SMEM per CTA: Q 16KB @0, then 3 KV ring buffers of 32KB {K 16KB, V 16KB}
#define SM_Q    0
#define SM_KV   16384
#define BUFB    32768
#define OFF_K   0
#define OFF_V   16384
#define SMEM_BYTES (SM_KV + 3 * BUFB)   // 112KB

__device__ __forceinline__ void load_kv_tile(uint32_t buf, size_t base, int tid) {
    const __half* kk = g_k + base;
    const __half* vv = g_v + base;
    #pragma unroll
    for (int j = 0; j < 8; ++j) {
        int c = tid + j * NTHR;           // 1024 16B chunks per sub-tile
        int row = c >> 4, cb = c & 15;
        uint32_t off = swz(row, cb);
        const size_t g = (size_t)row * HD + cb * 8;
        cp16(buf + OFF_K + off, kk + g);
        cp16(buf + OFF_V + off, vv + g);
    }
}

// S = Q K^T over one 64-key tile (zeroes S first)
__device__ __forceinline__ void qk_tile(float (&S)[8][4], const uint32_t (&aQ)[8][4],
                                        uint32_t kvb, int rB, int cB) {
    #pragma unroll
    for (int nf = 0; nf < 8; ++nf)
        #pragma unroll
        for (int i = 0; i < 4; ++i) S[nf][i] = 0.f;
    #pragma unroll
    for (int kf = 0; kf < 8; ++kf) {
        uint32_t bb[8][2];
        #pragma unroll
        for (int p = 0; p < 4; ++p) {
            uint32_t rr[4];
            ldsm4(kvb + OFF_K + swz(16 * p + rB, 2 * kf + cB), rr);
            bb[2*p][0] = rr[0]; bb[2*p][1] = rr[1];
            bb[2*p+1][0] = rr[2]; bb[2*p+1][1] = rr[3];
        }
        #pragma unroll
        for (int nf = 0; nf < 8; ++nf) mma_f16(S[nf], aQ[kf], bb[nf]);
    }
}

// Diagonal-tile QK: warp w only needs S fragments nf <= 2w+1 (rest fully masked).
// nfmax is warp-uniform, so the inner guard is a uniform branch.
__device__ __forceinline__ void qk_tile_diag(float (&S)[8][4], const uint32_t (&aQ)[8][4],
                                             uint32_t kvb, int rB, int cB, int nfmax) {
    #pragma unroll
    for (int nf = 0; nf < 8; ++nf)
        #pragma unroll
        for (int i = 0; i < 4; ++i) S[nf][i] = 0.f;
    #pragma unroll
    for (int kf = 0; kf < 8; ++kf) {
        uint32_t bb[8][2];
        #pragma unroll
        for (int p = 0; p < 4; ++p) {
            uint32_t rr[4];
            ldsm4(kvb + OFF_K + swz(16 * p + rB, 2 * kf + cB), rr);
            bb[2*p][0] = rr[0]; bb[2*p][1] = rr[1];
            bb[2*p+1][0] = rr[2]; bb[2*p+1][1] = rr[3];
        }
        #pragma unroll
        for (int nf = 0; nf < 8; ++nf)
            if (nf < nfmax) mma_f16(S[nf], aQ[kf], bb[nf]);
    }
}

// O += P V over one 64-key tile
__device__ __forceinline__ void pv_tile(float (&O)[16][4], const uint32_t (&aP)[4][4],
                                        uint32_t kvb, int rA, int cA) {
    #pragma unroll
    for (int kf = 0; kf < 4; ++kf) {
        #pragma unroll
        for (int ndp = 0; ndp < 8; ++ndp) {
            uint32_t vv[4];
            ldsm4t(kvb + OFF_V + swz(16 * kf + rA, 2 * ndp + cA), vv);
            mma_f16(O[2*ndp],     aP[kf], vv);
            mma_f16(O[2*ndp + 1], aP[kf], vv + 2);
        }
    }
}

__global__ __launch_bounds__(NTHR, 2)
void attn_main(const float* __restrict__ qf,
               const int* __restrict__ cuq, const int* __restrict__ cuk,
               const int* __restrict__ bt, float* __restrict__ out,
               int max_blocks)
{
    extern __shared__ __align__(1024) char smem[];
    const uint32_t sb = smem_u32(smem);
    const int tid = threadIdx.x;
    const int w = tid >> 5, lane = tid & 31;
    const int head = blockIdx.y, seq = blockIdx.z;
    const int kvh = head >> 2;                    // GRP=4

    const int q_start = cuq[seq];
    const int lq = cuq[seq + 1] - q_start;
    const int lk = cuk[seq + 1] - cuk[seq];
    const int hist = lk - lq;
    const int qt = gridDim.x - 1 - blockIdx.x;    // LPT: expensive q-tiles first
    const int q0 = qt * BQ;
    if (q0 >= lq) return;

    const int* btrow = bt + seq * max_blocks;     // hoisted block-table row

    // fragment lane decomposition
    const int g  = lane >> 2;
    const int t  = lane & 3;
    const int r8 = lane & 7;
    const int grp = lane >> 3;
    const int rA = ((grp & 1) << 3) + r8;
    const int cA = grp >> 1;
    const int rB = ((grp >> 1) << 3) + r8;
    const int cB = grp & 1;

    const int qpos0 = hist + q0 + 16 * w + g;
    const int qpos1 = qpos0 + 8;
    const int qpos_min = hist + q0;
    int lastk = hist + q0 + BQ - 1; if (lastk > lk - 1) lastk = lk - 1;
    const int n_tiles = lastk / BK + 1;
    const int nfmax_diag = 2 * w + 2;             // live S fragments on the diagonal tile

    // B-fragment of all-ones (f16 1.0 pairs) for l-summation via tensor core
    const uint32_t bOnes[2] = { 0x3C003C00u, 0x3C003C00u };

    // ring buffer bases (rotated in registers; no %3 in the loop)
    uint32_t bufA = sb + SM_KV;            // tile kt
    uint32_t bufB = bufA + BUFB;           // tile kt+1
    uint32_t bufC = bufB + BUFB;           // tile kt+2 (prefetch target)

    // ---- prefetch KV tiles 0,1 ----
    {
        size_t base0 = ((size_t)btrow[0] * NKVH + kvh) * (size_t)(BK * HD);
        load_kv_tile(bufA, base0, tid);
        CP_COMMIT();
        if (n_tiles > 1) {
            size_t base1 = ((size_t)btrow[1] * NKVH + kvh) * (size_t)(BK * HD);
            load_kv_tile(bufB, base1, tid);
        }
        CP_COMMIT();
    }

    // ---- load fp32 Q tile, scale+convert to f16, store to smem ----
    {
        const float s = 0.12753102f;   // (1/sqrt(128)) * log2(e)
        #pragma unroll
        for (int j = 0; j < 8; ++j) {
            int c = tid + j * NTHR;
            int row = c >> 4, cb = c & 15;
            const float* src = qf + ((size_t)(q_start + q0 + row) * NH + head) * HD + cb * 8;
            float4 a = *reinterpret_cast<const float4*>(src);
            float4 b = *reinterpret_cast<const float4*>(src + 4);
            uint4 u;
            __half2 h;
            h = __floats2half2_rn(a.x * s, a.y * s); u.x = *reinterpret_cast<uint32_t*>(&h);
            h = __floats2half2_rn(a.z * s, a.w * s); u.y = *reinterpret_cast<uint32_t*>(&h);
            h = __floats2half2_rn(b.x * s, b.y * s); u.z = *reinterpret_cast<uint32_t*>(&h);
            h = __floats2half2_rn(b.z * s, b.w * s); u.w = *reinterpret_cast<uint32_t*>(&h);
            *reinterpret_cast<uint4*>(smem + SM_Q + swz(row, cb)) = u;
        }
    }
    CP_WAIT1();          // tile 0 arrived (tile 1 may still fly)
    __syncthreads();     // Q stores + tile 0 visible
    uint32_t aQ[8][4];
    #pragma unroll
    for (int kf = 0; kf < 8; ++kf)
        ldsm4(sb + SM_Q + swz(16 * w + rA, 2 * kf + cA), aQ[kf]);

    float O[16][4];
    #pragma unroll
    for (int nd = 0; nd < 16; ++nd)
        #pragma unroll
        for (int i = 0; i < 4; ++i) O[nd][i] = 0.f;
    float L[4] = {0.f, 0.f, 0.f, 0.f};    // l via mma(P, ones): L[0]=row g, L[2]=row g+8
    float m0 = 0.f, m1 = 0.f;

    float S[8][4];
    qk_tile(S, aQ, bufA, rB, cB);    // scores of tile 0

    // ---- main loop: wait -> softmax(kt) -> QK(kt+1) -> prefetch -> PV(kt) ----
    for (int kt = 0; kt < n_tiles - 1; ++kt) {
        // tile kt+1 resident+visible; all warps done reading tile kt-1
        CP_WAIT0();
        __syncthreads();

        // -- softmax on S (tile kt) --
        if (kt == 0) {
            float mx0 = -1e30f, mx1 = -1e30f;
            #pragma unroll
            for (int nf = 0; nf < 8; ++nf) {
                mx0 = fmaxf(mx0, fmaxf(S[nf][0], S[nf][1]));
                mx1 = fmaxf(mx1, fmaxf(S[nf][2], S[nf][3]));
            }
            mx0 = fmaxf(mx0, __shfl_xor_sync(0xffffffffu, mx0, 1));
            mx0 = fmaxf(mx0, __shfl_xor_sync(0xffffffffu, mx0, 2));
            mx1 = fmaxf(mx1, __shfl_xor_sync(0xffffffffu, mx1, 1));
            mx1 = fmaxf(mx1, __shfl_xor_sync(0xffffffffu, mx1, 2));
            m0 = mx0; m1 = mx1;
        }
        const int kb = kt * BK;
        if (kb + BK - 1 > qpos_min) {
            #pragma unroll
            for (int nf = 0; nf < 8; ++nf) {
                const int kp = kb + 8 * nf + 2 * t;
                S[nf][0] = (kp     <= qpos0) ? S[nf][0] - m0 : -100.f;
                S[nf][1] = (kp + 1 <= qpos0) ? S[nf][1] - m0 : -100.f;
                S[nf][2] = (kp     <= qpos1) ? S[nf][2] - m1 : -100.f;
                S[nf][3] = (kp + 1 <= qpos1) ? S[nf][3] - m1 : -100.f;
            }
        } else {
            #pragma unroll
            for (int nf = 0; nf < 8; ++nf) {
                S[nf][0] -= m0; S[nf][1] -= m0;
                S[nf][2] -= m1; S[nf][3] -= m1;
            }
        }
        uint32_t aP[4][4];
        #pragma unroll
        for (int kf = 0; kf < 4; ++kf) {
            __half2 h;
            h = h2exp2(__floats2half2_rn(S[2*kf][0],   S[2*kf][1]));   aP[kf][0] = *reinterpret_cast<uint32_t*>(&h);
            h = h2exp2(__floats2half2_rn(S[2*kf][2],   S[2*kf][3]));   aP[kf][1] = *reinterpret_cast<uint32_t*>(&h);
            h = h2exp2(__floats2half2_rn(S[2*kf+1][0], S[2*kf+1][1])); aP[kf][2] = *reinterpret_cast<uint32_t*>(&h);
            h = h2exp2(__floats2half2_rn(S[2*kf+1][2], S[2*kf+1][3])); aP[kf][3] = *reinterpret_cast<uint32_t*>(&h);
        }
        // l accumulation on the tensor pipe (B = ones)
        #pragma unroll
        for (int kf = 0; kf < 4; ++kf) mma_f16(L, aP[kf], bOnes);

        // -- QK(kt+1); diagonal tile skips fully-masked fragments --
        if (kt + 2 == n_tiles)
            qk_tile_diag(S, aQ, bufB, rB, cB, nfmax_diag);
        else
            qk_tile(S, aQ, bufB, rB, cB);

        // -- prefetch kt+2 into bufC (freed: it held tile kt-1, consumed pre-sync) --
        const int nt = kt + 2;
        if (nt < n_tiles) {
            size_t base = ((size_t)btrow[nt] * NKVH + kvh) * (size_t)(BK * HD);
            load_kv_tile(bufC, base, tid);
        }
        CP_COMMIT();   // possibly-empty commit keeps group counting fixed

        // -- PV(kt) --
        pv_tile(O, aP, bufA, rA, cA);

        // rotate ring
        uint32_t tmp = bufA; bufA = bufB; bufB = bufC; bufC = tmp;
    }

    // ---- tail tile (diagonal): warp w only needs kf-groups 0..w ----
    {
        const int kt = n_tiles - 1;
        if (kt == 0) {
            float mx0 = -1e30f, mx1 = -1e30f;
            #pragma unroll
            for (int nf = 0; nf < 8; ++nf) {
                mx0 = fmaxf(mx0, fmaxf(S[nf][0], S[nf][1]));
                mx1 = fmaxf(mx1, fmaxf(S[nf][2], S[nf][3]));
            }
            mx0 = fmaxf(mx0, __shfl_xor_sync(0xffffffffu, mx0, 1));
            mx0 = fmaxf(mx0, __shfl_xor_sync(0xffffffffu, mx0, 2));
            mx1 = fmaxf(mx1, __shfl_xor_sync(0xffffffffu, mx1, 1));
            mx1 = fmaxf(mx1, __shfl_xor_sync(0xffffffffu, mx1, 2));
            m0 = mx0; m1 = mx1;
        }
        const int kb = kt * BK;
        #pragma unroll
        for (int nf = 0; nf < 8; ++nf) {
            const int kp = kb + 8 * nf + 2 * t;
            S[nf][0] = (kp     <= qpos0) ? S[nf][0] - m0 : -100.f;
            S[nf][1] = (kp + 1 <= qpos0) ? S[nf][1] - m0 : -100.f;
            S[nf][2] = (kp     <= qpos1) ? S[nf][2] - m1 : -100.f;
            S[nf][3] = (kp + 1 <= qpos1) ? S[nf][3] - m1 : -100.f;
        }
        #pragma unroll
        for (int kf = 0; kf < 4; ++kf) {
            if (kf > w) break;            // keys kb+16kf.. all-masked for this warp
            uint32_t aPk[4];
            __half2 h;
            h = h2exp2(__floats2half2_rn(S[2*kf][0],   S[2*kf][1]));   aPk[0] = *reinterpret_cast<uint32_t*>(&h);
            h = h2exp2(__floats2half2_rn(S[2*kf][2],   S[2*kf][3]));   aPk[1] = *reinterpret_cast<uint32_t*>(&h);
            h = h2exp2(__floats2half2_rn(S[2*kf+1][0], S[2*kf+1][1])); aPk[2] = *reinterpret_cast<uint32_t*>(&h);
            h = h2exp2(__floats2half2_rn(S[2*kf+1][2], S[2*kf+1][3])); aPk[3] = *reinterpret_cast<uint32_t*>(&h);
            mma_f16(L, aPk, bOnes);
            #pragma unroll
            for (int ndp = 0; ndp < 8; ++ndp) {
                uint32_t vv[4];
                ldsm4t(bufA + OFF_V + swz(16 * kf + rA, 2 * ndp + cA), vv);
                mma_f16(O[2*ndp],     aPk, vv);
                mma_f16(O[2*ndp + 1], aPk, vv + 2);
            }
        }
    }

    // ---- epilogue (L already holds full row sums; no shuffles needed) ----
    const float inv0 = 1.0f / L[0], inv1 = 1.0f / L[2];

    const int row0 = q_start + q0 + 16 * w + g;
    float* o0 = out + ((size_t)row0 * NH + head) * HD;
    float* o1 = o0 + (size_t)8 * NH * HD;
    #pragma unroll
    for (int nd = 0; nd < 16; ++nd) {
        float2 u0 = make_float2(O[nd][0] * inv0, O[nd][1] * inv0);
        float2 u1 = make_float2(O[nd][2] * inv1, O[nd][3] * inv1);
        *reinterpret_cast<float2*>(o0 + 8 * nd + 2 * t) = u0;
        *reinterpret_cast<float2*>(o1 + 8 * nd + 2 * t) = u1;
    }
}

extern "C" void kernel_launch(void* const* d_in, const int* in_sizes, int n_in,
                              void* d_out, int out_size)
{
    const float* q   = (const float*)d_in[0];
    const float* kc  = (const float*)d_in[1];
    const float* vc  = (const float*)d_in[2];
    const int*   cuq = (const int*)d_in[3];
    const int*   cuk = (const int*)d_in[4];
    const int*   bt  = (const int*)d_in[5];
    float*       out = (float*)d_out;

    const int tot_q      = in_sizes[0] / (NH * HD);          // 2048
    const int nseq       = in_sizes[3] - 1;                  // 2
    const int lq         = tot_q / nseq;                     // 1024
    const int max_blocks = in_sizes[5] / nseq;               // 32
    const int nblk_tot   = in_sizes[1] / (BK * NKVH * HD);   // 64
    const int q_tiles    = (lq + BQ - 1) / BQ;               // 16

    prep_kv<<<nblk_tot * NKVH * 2, 256>>>(kc, vc);

    cudaFuncSetAttribute(attn_main, cudaFuncAttributeMaxDynamicSharedMemorySize, SMEM_BYTES);
    dim3 grid(q_tiles, NH, nseq);
    attn_main<<<grid, NTHR, SMEM_BYTES>>>(q, cuq, cuk, bt, out, max_blocks);
}

// round 16
// speedup vs baseline: 1.0410x; 1.0410x over previous
#include <cuda_runtime.h>
#include <cuda_fp16.h>
#include <cstdint>

#define NH    32
#define NKVH  8
#define HD    128
#define BK    64
#define BQ    64
#define NTHR  128
#define MAXBLK 64

// ---- static device scratch (no allocations) ----
__device__ __half g_k[(size_t)MAXBLK * NKVH * BK * HD];
__device__ __half g_v[(size_t)MAXBLK * NKVH * BK * HD];

// ---- helpers ----
__device__ __forceinline__ uint32_t smem_u32(const void* p) {
    uint32_t a;
    asm("{ .reg .u64 t; cvta.to.shared.u64 t, %1; cvt.u32.u64 %0, t; }" : "=r"(a) : "l"(p));
    return a;
}
__device__ __forceinline__ void cp16(uint32_t dst, const void* src) {
    asm volatile("cp.async.cg.shared.global [%0], [%1], 16;" :: "r"(dst), "l"(src) : "memory");
}
#define CP_COMMIT() asm volatile("cp.async.commit_group;" ::: "memory")
#define CP_WAIT0()  asm volatile("cp.async.wait_group 0;" ::: "memory")
#define CP_WAIT1()  asm volatile("cp.async.wait_group 1;" ::: "memory")

__device__ __forceinline__ void ldsm4(uint32_t addr, uint32_t* r) {
    asm volatile("ldmatrix.sync.aligned.m8n8.x4.shared.b16 {%0,%1,%2,%3}, [%4];"
        : "=r"(r[0]), "=r"(r[1]), "=r"(r[2]), "=r"(r[3]) : "r"(addr));
}
__device__ __forceinline__ void ldsm4t(uint32_t addr, uint32_t* r) {
    asm volatile("ldmatrix.sync.aligned.m8n8.x4.trans.shared.b16 {%0,%1,%2,%3}, [%4];"
        : "=r"(r[0]), "=r"(r[1]), "=r"(r[2]), "=r"(r[3]) : "r"(addr));
}
__device__ __forceinline__ void mma_f16(float* c, const uint32_t* a, const uint32_t* b) {
    asm volatile("mma.sync.aligned.m16n8k16.row.col.f32.f16.f16.f32 "
        "{%0,%1,%2,%3}, {%4,%5,%6,%7}, {%8,%9}, {%0,%1,%2,%3};"
        : "+f"(c[0]), "+f"(c[1]), "+f"(c[2]), "+f"(c[3])
        : "r"(a[0]), "r"(a[1]), "r"(a[2]), "r"(a[3]), "r"(b[0]), "r"(b[1]));
}
// swizzled byte offset inside a tile with 256B rows (16 x 16B chunks)
__device__ __forceinline__ uint32_t swz(int row, int cb) {
    return (uint32_t)(row * 256 + ((cb ^ (row & 7)) << 4));
}

// ---- prep kernel: gather-convert K,V to [blk*kvh][key][d] fp16 ----
__global__ __launch_bounds__(256) void prep_kv(const float* __restrict__ kc,
                                               const float* __restrict__ vc) {
    int bb = blockIdx.x;            // 0..1023
    int b = bb >> 1, half = bb & 1;
    int blk = b >> 3, kvh = b & 7;
    #pragma unroll
    for (int j = 0; j < 2; ++j) {
        int c = threadIdx.x + j * 256 + half * 512;
        int row = c >> 4, d = (c & 15) * 8;
        const size_t src = ((size_t)(blk * BK + row) * NKVH + kvh) * HD + d;
        const size_t dst = ((size_t)b * BK + row) * HD + d;
        float4 ka = *reinterpret_cast<const float4*>(kc + src);
        float4 kb = *reinterpret_cast<const float4*>(kc + src + 4);
        float4 va = *reinterpret_cast<const float4*>(vc + src);
        float4 vb = *reinterpret_cast<const float4*>(vc + src + 4);
        uint4 uk, uv;
        __half2 h;
        h = __floats2half2_rn(ka.x, ka.y); uk.x = *reinterpret_cast<uint32_t*>(&h);
        h = __floats2half2_rn(ka.z, ka.w); uk.y = *reinterpret_cast<uint32_t*>(&h);
        h = __floats2half2_rn(kb.x, kb.y); uk.z = *reinterpret_cast<uint32_t*>(&h);
        h = __floats2half2_rn(kb.z, kb.w); uk.w = *reinterpret_cast<uint32_t*>(&h);
        h = __floats2half2_rn(va.x, va.y); uv.x = *reinterpret_cast<uint32_t*>(&h);
        h = __floats2half2_rn(va.z, va.w); uv.y = *reinterpret_cast<uint32_t*>(&h);
        h = __floats2half2_rn(vb.x, vb.y); uv.z = *reinterpret_cast<uint32_t*>(&h);
        h = __floats2half2_rn(vb.z, vb.w); uv.w = *reinterpret_cast<uint32_t*>(&h);
        *reinterpret_cast<uint4*>(g_k + dst) = uk;
        *reinterpret_cast<uint4*>(g_v + dst) = uv;
    }
}

// ---- main kernel ----
// SMEM per CTA: Q 16KB @0, then 3 KV ring buffers of 32KB {K 16KB, V 16KB}
#define SM_Q    0
#define SM_KV   16384
#define BUFB    32768
#define OFF_K   0
#define OFF_V   16384
#define SMEM_BYTES (SM_KV + 3 * BUFB)   // 112KB

__device__ __forceinline__ void load_kv_tile(uint32_t buf, size_t base, int tid) {
    const __half* kk = g_k + base;
    const __half* vv = g_v + base;
    #pragma unroll
    for (int j = 0; j < 8; ++j) {
        int c = tid + j * NTHR;           // 1024 16B chunks per sub-tile
        int row = c >> 4, cb = c & 15;
        uint32_t off = swz(row, cb);
        const size_t g = (size_t)row * HD + cb * 8;
        cp16(buf + OFF_K + off, kk + g);
        cp16(buf + OFF_V + off, vv + g);
    }
}

// S = Q K^T over one 64-key tile (zeroes S first)
__device__ __forceinline__ void qk_tile(float (&S)[8][4], const uint32_t (&aQ)[8][4],
                                        uint32_t kvb, int rB, int cB) {
    #pragma unroll
    for (int nf = 0; nf < 8; ++nf)
        #pragma unroll
        for (int i = 0; i < 4; ++i) S[nf][i] = 0.f;
    #pragma unroll
    for (int kf = 0; kf < 8; ++kf) {
        uint32_t bb[8][2];
        #pragma unroll
        for (int p = 0; p < 4; ++p) {
            uint32_t rr[4];
            ldsm4(kvb + OFF_K + swz(16 * p + rB, 2 * kf + cB), rr);
            bb[2*p][0] = rr[0]; bb[2*p][1] = rr[1];
            bb[2*p+1][0] = rr[2]; bb[2*p+1][1] = rr[3];
        }
        #pragma unroll
        for (int nf = 0; nf < 8; ++nf) mma_f16(S[nf], aQ[kf], bb[nf]);
    }
}

// O += P V over one 64-key tile
__device__ __forceinline__ void pv_tile(float (&O)[16][4], const uint32_t (&aP)[4][4],
                                        uint32_t kvb, int rA, int cA) {
    #pragma unroll
    for (int kf = 0; kf < 4; ++kf) {
        #pragma unroll
        for (int ndp = 0; ndp < 8; ++ndp) {
            uint32_t vv[4];
            ldsm4t(kvb + OFF_V + swz(16 * kf + rA, 2 * ndp + cA), vv);
            mma_f16(O[2*ndp],     aP[kf], vv);
            mma_f16(O[2*ndp + 1], aP[kf], vv + 2);
        }
    }
}

__global__ __launch_bounds__(NTHR, 2)
void attn_main(const float* __restrict__ qf,
               const int* __restrict__ cuq, const int* __restrict__ cuk,
               const int* __restrict__ bt, float* __restrict__ out,
               int max_blocks)
{
    extern __shared__ __align__(1024) char smem[];
    const uint32_t sb = smem_u32(smem);
    const int tid = threadIdx.x;
    const int w = tid >> 5, lane = tid & 31;
    const int head = blockIdx.y, seq = blockIdx.z;
    const int kvh = head >> 2;                    // GRP=4

    const int q_start = cuq[seq];
    const int lq = cuq[seq + 1] - q_start;
    const int lk = cuk[seq + 1] - cuk[seq];
    const int hist = lk - lq;
    const int qt = gridDim.x - 1 - blockIdx.x;    // LPT: expensive q-tiles first
    const int q0 = qt * BQ;
    if (q0 >= lq) return;

    const int* btrow = bt + seq * max_blocks;     // hoisted block-table row

    // fragment lane decomposition
    const int g  = lane >> 2;
    const int t  = lane & 3;
    const int r8 = lane & 7;
    const int grp = lane >> 3;
    const int rA = ((grp & 1) << 3) + r8;
    const int cA = grp >> 1;
    const int rB = ((grp >> 1) << 3) + r8;
    const int cB = grp & 1;

    const int qpos0 = hist + q0 + 16 * w + g;
    const int qpos1 = qpos0 + 8;
    const int qpos_min = hist + q0;
    int lastk = hist + q0 + BQ - 1; if (lastk > lk - 1) lastk = lk - 1;
    const int n_tiles = lastk / BK + 1;

    // ring buffer bases (rotated in registers; no %3 in the loop)
    uint32_t bufA = sb + SM_KV;            // tile kt
    uint32_t bufB = bufA + BUFB;           // tile kt+1
    uint32_t bufC = bufB + BUFB;           // tile kt+2 (prefetch target)

    // ---- prefetch KV tiles 0,1 ----
    {
        size_t base0 = ((size_t)btrow[0] * NKVH + kvh) * (size_t)(BK * HD);
        load_kv_tile(bufA, base0, tid);
        CP_COMMIT();
        if (n_tiles > 1) {
            size_t base1 = ((size_t)btrow[1] * NKVH + kvh) * (size_t)(BK * HD);
            load_kv_tile(bufB, base1, tid);
        }
        CP_COMMIT();
    }

    // ---- load fp32 Q tile, scale+convert to f16, store to smem ----
    {
        const float s = 0.12753102f;   // (1/sqrt(128)) * log2(e)
        #pragma unroll
        for (int j = 0; j < 8; ++j) {
            int c = tid + j * NTHR;
            int row = c >> 4, cb = c & 15;
            const float* src = qf + ((size_t)(q_start + q0 + row) * NH + head) * HD + cb * 8;
            float4 a = *reinterpret_cast<const float4*>(src);
            float4 b = *reinterpret_cast<const float4*>(src + 4);
            uint4 u;
            __half2 h;
            h = __floats2half2_rn(a.x * s, a.y * s); u.x = *reinterpret_cast<uint32_t*>(&h);
            h = __floats2half2_rn(a.z * s, a.w * s); u.y = *reinterpret_cast<uint32_t*>(&h);
            h = __floats2half2_rn(b.x * s, b.y * s); u.z = *reinterpret_cast<uint32_t*>(&h);
            h = __floats2half2_rn(b.z * s, b.w * s); u.w = *reinterpret_cast<uint32_t*>(&h);
            *reinterpret_cast<uint4*>(smem + SM_Q + swz(row, cb)) = u;
        }
    }
    CP_WAIT1();          // tile 0 arrived (tile 1 may still fly)
    __syncthreads();     // Q stores + tile 0 visible
    uint32_t aQ[8][4];
    #pragma unroll
    for (int kf = 0; kf < 8; ++kf)
        ldsm4(sb + SM_Q + swz(16 * w + rA, 2 * kf + cA), aQ[kf]);

    float O[16][4];
    #pragma unroll
    for (int nd = 0; nd < 16; ++nd)
        #pragma unroll
        for (int i = 0; i < 4; ++i) O[nd][i] = 0.f;
    float ls0 = 0.f, ls1 = 0.f, m0 = 0.f, m1 = 0.f;

    float S[8][4];
    qk_tile(S, aQ, bufA, rB, cB);    // scores of tile 0

    // ---- main loop: wait/prefetch -> softmax(kt) -> QK(kt+1) -> PV(kt) ----
    for (int kt = 0; kt < n_tiles - 1; ++kt) {
        // tile kt+1 resident+visible; all warps done reading tile kt-1
        CP_WAIT0();
        __syncthreads();
        const int nt = kt + 2;
        if (nt < n_tiles) {
            size_t base = ((size_t)btrow[nt] * NKVH + kvh) * (size_t)(BK * HD);
            load_kv_tile(bufC, base, tid);
        }
        CP_COMMIT();   // possibly-empty commit keeps group counting fixed

        // -- softmax on S (tile kt) --
        if (kt == 0) {
            float mx0 = -1e30f, mx1 = -1e30f;
            #pragma unroll
            for (int nf = 0; nf < 8; ++nf) {
                mx0 = fmaxf(mx0, fmaxf(S[nf][0], S[nf][1]));
                mx1 = fmaxf(mx1, fmaxf(S[nf][2], S[nf][3]));
            }
            mx0 = fmaxf(mx0, __shfl_xor_sync(0xffffffffu, mx0, 1));
            mx0 = fmaxf(mx0, __shfl_xor_sync(0xffffffffu, mx0, 2));
            mx1 = fmaxf(mx1, __shfl_xor_sync(0xffffffffu, mx1, 1));
            mx1 = fmaxf(mx1, __shfl_xor_sync(0xffffffffu, mx1, 2));
            m0 = mx0; m1 = mx1;
        }
        const int kb = kt * BK;
        if (kb + BK - 1 > qpos_min) {
            #pragma unroll
            for (int nf = 0; nf < 8; ++nf) {
                const int kp = kb + 8 * nf + 2 * t;
                S[nf][0] = (kp     <= qpos0) ? S[nf][0] - m0 : -100.f;
                S[nf][1] = (kp + 1 <= qpos0) ? S[nf][1] - m0 : -100.f;
                S[nf][2] = (kp     <= qpos1) ? S[nf][2] - m1 : -100.f;
                S[nf][3] = (kp + 1 <= qpos1) ? S[nf][3] - m1 : -100.f;
            }
        } else {
            #pragma unroll
            for (int nf = 0; nf < 8; ++nf) {
                S[nf][0] -= m0; S[nf][1] -= m0;
                S[nf][2] -= m1; S[nf][3] -= m1;
            }
        }
        uint32_t aP[4][4];
        #pragma unroll
        for (int kf = 0; kf < 4; ++kf) {
            __half2 h;
            h = h2exp2(__floats2half2_rn(S[2*kf][0],   S[2*kf][1]));   aP[kf][0] = *reinterpret_cast<uint32_t*>(&h);
            h = h2exp2(__floats2half2_rn(S[2*kf][2],   S[2*kf][3]));   aP[kf][1] = *reinterpret_cast<uint32_t*>(&h);
            h = h2exp2(__floats2half2_rn(S[2*kf+1][0], S[2*kf+1][1])); aP[kf][2] = *reinterpret_cast<uint32_t*>(&h);
            h = h2exp2(__floats2half2_rn(S[2*kf+1][2], S[2*kf+1][3])); aP[kf][3] = *reinterpret_cast<uint32_t*>(&h);
        }
        #pragma unroll
        for (int kf = 0; kf < 4; ++kf) {
            const __half2 p00 = *reinterpret_cast<const __half2*>(&aP[kf][0]);
            const __half2 p01 = *reinterpret_cast<const __half2*>(&aP[kf][1]);
            const __half2 p10 = *reinterpret_cast<const __half2*>(&aP[kf][2]);
            const __half2 p11 = *reinterpret_cast<const __half2*>(&aP[kf][3]);
            ls0 += __low2float(p00) + __high2float(p00) + __low2float(p10) + __high2float(p10);
            ls1 += __low2float(p01) + __high2float(p01) + __low2float(p11) + __high2float(p11);
        }

        // -- QK(kt+1) then PV(kt); independent blocks, ptxas interleaves --
        qk_tile(S, aQ, bufB, rB, cB);
        pv_tile(O, aP, bufA, rA, cA);

        // rotate ring
        uint32_t tmp = bufA; bufA = bufB; bufB = bufC; bufC = tmp;
    }

    // ---- tail tile (diagonal): warp w only needs kf-groups 0..w ----
    {
        const int kt = n_tiles - 1;
        if (kt == 0) {
            float mx0 = -1e30f, mx1 = -1e30f;
            #pragma unroll
            for (int nf = 0; nf < 8; ++nf) {
                mx0 = fmaxf(mx0, fmaxf(S[nf][0], S[nf][1]));
                mx1 = fmaxf(mx1, fmaxf(S[nf][2], S[nf][3]));
            }
            mx0 = fmaxf(mx0, __shfl_xor_sync(0xffffffffu, mx0, 1));
            mx0 = fmaxf(mx0, __shfl_xor_sync(0xffffffffu, mx0, 2));
            mx1 = fmaxf(mx1, __shfl_xor_sync(0xffffffffu, mx1, 1));
            mx1 = fmaxf(mx1, __shfl_xor_sync(0xffffffffu, mx1, 2));
            m0 = mx0; m1 = mx1;
        }
        const int kb = kt * BK;
        #pragma unroll
        for (int nf = 0; nf < 8; ++nf) {
            const int kp = kb + 8 * nf + 2 * t;
            S[nf][0] = (kp     <= qpos0) ? S[nf][0] - m0 : -100.f;
            S[nf][1] = (kp + 1 <= qpos0) ? S[nf][1] - m0 : -100.f;
            S[nf][2] = (kp     <= qpos1) ? S[nf][2] - m1 : -100.f;
            S[nf][3] = (kp + 1 <= qpos1) ? S[nf][3] - m1 : -100.f;
        }
        #pragma unroll
        for (int kf = 0; kf < 4; ++kf) {
            if (kf > w) break;            // keys kb+16kf.. all-masked for this warp
            uint32_t aPk[4];
            __half2 h;
            h = h2exp2(__floats2half2_rn(S[2*kf][0],   S[2*kf][1]));   aPk[0] = *reinterpret_cast<uint32_t*>(&h);
            h = h2exp2(__floats2half2_rn(S[2*kf][2],   S[2*kf][3]));   aPk[1] = *reinterpret_cast<uint32_t*>(&h);
            h = h2exp2(__floats2half2_rn(S[2*kf+1][0], S[2*kf+1][1])); aPk[2] = *reinterpret_cast<uint32_t*>(&h);
            h = h2exp2(__floats2half2_rn(S[2*kf+1][2], S[2*kf+1][3])); aPk[3] = *reinterpret_cast<uint32_t*>(&h);
            const __half2 p00 = *reinterpret_cast<const __half2*>(&aPk[0]);
            const __half2 p01 = *reinterpret_cast<const __half2*>(&aPk[1]);
            const __half2 p10 = *reinterpret_cast<const __half2*>(&aPk[2]);
            const __half2 p11 = *reinterpret_cast<const __half2*>(&aPk[3]);
            ls0 += __low2float(p00) + __high2float(p00) + __low2float(p10) + __high2float(p10);
            ls1 += __low2float(p01) + __high2float(p01) + __low2float(p11) + __high2float(p11);
            #pragma unroll
            for (int ndp = 0; ndp < 8; ++ndp) {
                uint32_t vv[4];
                ldsm4t(bufA + OFF_V + swz(16 * kf + rA, 2 * ndp + cA), vv);
                mma_f16(O[2*ndp],     aPk, vv);
                mma_f16(O[2*ndp + 1], aPk, vv + 2);
            }
        }
    }

    // ---- epilogue ----
    ls0 += __shfl_xor_sync(0xffffffffu, ls0, 1);
    ls0 += __shfl_xor_sync(0xffffffffu, ls0, 2);
    ls1 += __shfl_xor_sync(0xffffffffu, ls1, 1);
    ls1 += __shfl_xor_sync(0xffffffffu, ls1, 2);
    const float inv0 = 1.0f / ls0, inv1 = 1.0f / ls1;

    const int row0 = q_start + q0 + 16 * w + g;
    float* o0 = out + ((size_t)row0 * NH + head) * HD;
    float* o1 = o0 + (size_t)8 * NH * HD;
    #pragma unroll
    for (int nd = 0; nd < 16; ++nd) {
        float2 u0 = make_float2(O[nd][0] * inv0, O[nd][1] * inv0);
        float2 u1 = make_float2(O[nd][2] * inv1, O[nd][3] * inv1);
        *reinterpret_cast<float2*>(o0 + 8 * nd + 2 * t) = u0;
        *reinterpret_cast<float2*>(o1 + 8 * nd + 2 * t) = u1;
    }
}

extern "C" void kernel_launch(void* const* d_in, const int* in_sizes, int n_in,
                              void* d_out, int out_size)
{
    const float* q   = (const float*)d_in[0];
    const float* kc  = (const float*)d_in[1];
    const float* vc  = (const float*)d_in[2];
    const int*   cuq = (const int*)d_in[3];
    const int*   cuk = (const int*)d_in[4];
    const int*   bt  = (const int*)d_in[5];
    float*       out = (float*)d_out;

    const int tot_q      = in_sizes[0] / (NH * HD);          // 2048
    const int nseq       = in_sizes[3] - 1;                  // 2
    const int lq         = tot_q / nseq;                     // 1024
    const int max_blocks = in_sizes[5] / nseq;               // 32
    const int nblk_tot   = in_sizes[1] / (BK * NKVH * HD);   // 64
    const int q_tiles    = (lq + BQ - 1) / BQ;               // 16

    prep_kv<<<nblk_tot * NKVH * 2, 256>>>(kc, vc);

    cudaFuncSetAttribute(attn_main, cudaFuncAttributeMaxDynamicSharedMemorySize, SMEM_BYTES);
    dim3 grid(q_tiles, NH, nseq);
    attn_main<<<grid, NTHR, SMEM_BYTES>>>(q, cuq, cuk, bt, out, max_blocks);
}

// round 17
// speedup vs baseline: 1.0454x; 1.0041x over previous
#include <cuda_runtime.h>
#include <cuda_fp16.h>
#include <cstdint>

#define NH    32
#define NKVH  8
#define HD    128
#define BK    64
#define BQ    64
#define NTHR  128
#define MAXBLK 64

// ---- static device scratch (no allocations) ----
__device__ __half g_k[(size_t)MAXBLK * NKVH * BK * HD];
__device__ __half g_v[(size_t)MAXBLK * NKVH * BK * HD];

// ---- helpers ----
__device__ __forceinline__ uint32_t smem_u32(const void* p) {
    uint32_t a;
    asm("{ .reg .u64 t; cvta.to.shared.u64 t, %1; cvt.u32.u64 %0, t; }" : "=r"(a) : "l"(p));
    return a;
}
__device__ __forceinline__ void cp16(uint32_t dst, const void* src) {
    asm volatile("cp.async.cg.shared.global [%0], [%1], 16;" :: "r"(dst), "l"(src) : "memory");
}
#define CP_COMMIT() asm volatile("cp.async.commit_group;" ::: "memory")
#define CP_WAIT0()  asm volatile("cp.async.wait_group 0;" ::: "memory")
#define CP_WAIT1()  asm volatile("cp.async.wait_group 1;" ::: "memory")

__device__ __forceinline__ void ldsm4(uint32_t addr, uint32_t* r) {
    asm volatile("ldmatrix.sync.aligned.m8n8.x4.shared.b16 {%0,%1,%2,%3}, [%4];"
        : "=r"(r[0]), "=r"(r[1]), "=r"(r[2]), "=r"(r[3]) : "r"(addr));
}
__device__ __forceinline__ void ldsm4t(uint32_t addr, uint32_t* r) {
    asm volatile("ldmatrix.sync.aligned.m8n8.x4.trans.shared.b16 {%0,%1,%2,%3}, [%4];"
        : "=r"(r[0]), "=r"(r[1]), "=r"(r[2]), "=r"(r[3]) : "r"(addr));
}
__device__ __forceinline__ void mma_f16(float* c, const uint32_t* a, const uint32_t* b) {
    asm volatile("mma.sync.aligned.m16n8k16.row.col.f32.f16.f16.f32 "
        "{%0,%1,%2,%3}, {%4,%5,%6,%7}, {%8,%9}, {%0,%1,%2,%3};"
        : "+f"(c[0]), "+f"(c[1]), "+f"(c[2]), "+f"(c[3])
        : "r"(a[0]), "r"(a[1]), "r"(a[2]), "r"(a[3]), "r"(b[0]), "r"(b[1]));
}
// swizzled byte offset inside a tile with 256B rows (16 x 16B chunks)
__device__ __forceinline__ uint32_t swz(int row, int cb) {
    return (uint32_t)(row * 256 + ((cb ^ (row & 7)) << 4));
}

// ---- prep kernel: gather-convert K,V to [blk*kvh][key][d] fp16 ----
__global__ __launch_bounds__(256) void prep_kv(const float* __restrict__ kc,
                                               const float* __restrict__ vc) {
    int bb = blockIdx.x;            // 0..1023
    int b = bb >> 1, half = bb & 1;
    int blk = b >> 3, kvh = b & 7;
    #pragma unroll
    for (int j = 0; j < 2; ++j) {
        int c = threadIdx.x + j * 256 + half * 512;
        int row = c >> 4, d = (c & 15) * 8;
        const size_t src = ((size_t)(blk * BK + row) * NKVH + kvh) * HD + d;
        const size_t dst = ((size_t)b * BK + row) * HD + d;
        float4 ka = *reinterpret_cast<const float4*>(kc + src);
        float4 kb = *reinterpret_cast<const float4*>(kc + src + 4);
        float4 va = *reinterpret_cast<const float4*>(vc + src);
        float4 vb = *reinterpret_cast<const float4*>(vc + src + 4);
        uint4 uk, uv;
        __half2 h;
        h = __floats2half2_rn(ka.x, ka.y); uk.x = *reinterpret_cast<uint32_t*>(&h);
        h = __floats2half2_rn(ka.z, ka.w); uk.y = *reinterpret_cast<uint32_t*>(&h);
        h = __floats2half2_rn(kb.x, kb.y); uk.z = *reinterpret_cast<uint32_t*>(&h);
        h = __floats2half2_rn(kb.z, kb.w); uk.w = *reinterpret_cast<uint32_t*>(&h);
        h = __floats2half2_rn(va.x, va.y); uv.x = *reinterpret_cast<uint32_t*>(&h);
        h = __floats2half2_rn(va.z, va.w); uv.y = *reinterpret_cast<uint32_t*>(&h);
        h = __floats2half2_rn(vb.x, vb.y); uv.z = *reinterpret_cast<uint32_t*>(&h);
        h = __floats2half2_rn(vb.z, vb.w); uv.w = *reinterpret_cast<uint32_t*>(&h);
        *reinterpret_cast<uint4*>(g_k + dst) = uk;
        *reinterpret_cast<uint4*>(g_v + dst) = uv;
    }
}

// ---- main kernel ----
// SMEM per CTA: Q 16KB @0, then 3 KV ring buffers of 32KB {K 16KB, V 16KB}
#define SM_Q    0
#define SM_KV   16384
#define BUFB    32768
#define OFF_K   0
#define OFF_V   16384
#define SMEM_BYTES (SM_KV + 3 * BUFB)   // 112KB

__device__ __forceinline__ void load_kv_tile(uint32_t buf, size_t base, int tid) {
    const __half* kk = g_k + base;
    const __half* vv = g_v + base;
    #pragma unroll
    for (int j = 0; j < 8; ++j) {
        int c = tid + j * NTHR;           // 1024 16B chunks per sub-tile
        int row = c >> 4, cb = c & 15;
        uint32_t off = swz(row, cb);
        const size_t g = (size_t)row * HD + cb * 8;
        cp16(buf + OFF_K + off, kk + g);
        cp16(buf + OFF_V + off, vv + g);
    }
}

// S = Q K^T over one 64-key tile (zeroes S first)
__device__ __forceinline__ void qk_tile(float (&S)[8][4], const uint32_t (&aQ)[8][4],
                                        uint32_t kvb, int rB, int cB) {
    #pragma unroll
    for (int nf = 0; nf < 8; ++nf)
        #pragma unroll
        for (int i = 0; i < 4; ++i) S[nf][i] = 0.f;
    #pragma unroll
    for (int kf = 0; kf < 8; ++kf) {
        uint32_t bb[8][2];
        #pragma unroll
        for (int p = 0; p < 4; ++p) {
            uint32_t rr[4];
            ldsm4(kvb + OFF_K + swz(16 * p + rB, 2 * kf + cB), rr);
            bb[2*p][0] = rr[0]; bb[2*p][1] = rr[1];
            bb[2*p+1][0] = rr[2]; bb[2*p+1][1] = rr[3];
        }
        #pragma unroll
        for (int nf = 0; nf < 8; ++nf) mma_f16(S[nf], aQ[kf], bb[nf]);
    }
}

// O += P V over one 64-key tile
__device__ __forceinline__ void pv_tile(float (&O)[16][4], const uint32_t (&aP)[4][4],
                                        uint32_t kvb, int rA, int cA) {
    #pragma unroll
    for (int kf = 0; kf < 4; ++kf) {
        #pragma unroll
        for (int ndp = 0; ndp < 8; ++ndp) {
            uint32_t vv[4];
            ldsm4t(kvb + OFF_V + swz(16 * kf + rA, 2 * ndp + cA), vv);
            mma_f16(O[2*ndp],     aP[kf], vv);
            mma_f16(O[2*ndp + 1], aP[kf], vv + 2);
        }
    }
}

__global__ __launch_bounds__(NTHR, 2)
void attn_main(const float* __restrict__ qf,
               const int* __restrict__ cuq, const int* __restrict__ cuk,
               const int* __restrict__ bt, float* __restrict__ out,
               int max_blocks)
{
    extern __shared__ __align__(1024) char smem[];
    const uint32_t sb = smem_u32(smem);
    const int tid = threadIdx.x;
    const int w = tid >> 5, lane = tid & 31;
    const int head = blockIdx.y, seq = blockIdx.z;
    const int kvh = head >> 2;                    // GRP=4

    const int q_start = cuq[seq];
    const int lq = cuq[seq + 1] - q_start;
    const int lk = cuk[seq + 1] - cuk[seq];
    const int hist = lk - lq;
    const int qt = gridDim.x - 1 - blockIdx.x;    // LPT: expensive q-tiles first
    const int q0 = qt * BQ;
    if (q0 >= lq) return;

    const int* btrow = bt + seq * max_blocks;     // hoisted block-table row

    // fragment lane decomposition
    const int g  = lane >> 2;
    const int t  = lane & 3;
    const int r8 = lane & 7;
    const int grp = lane >> 3;
    const int rA = ((grp & 1) << 3) + r8;
    const int cA = grp >> 1;
    const int rB = ((grp >> 1) << 3) + r8;
    const int cB = grp & 1;

    const int qpos0 = hist + q0 + 16 * w + g;
    const int qpos1 = qpos0 + 8;
    const int qpos_min = hist + q0;
    int lastk = hist + q0 + BQ - 1; if (lastk > lk - 1) lastk = lk - 1;
    const int n_tiles = lastk / BK + 1;

    // ring buffer bases (rotated in registers; no %3 in the loop)
    uint32_t bufA = sb + SM_KV;            // tile kt
    uint32_t bufB = bufA + BUFB;           // tile kt+1
    uint32_t bufC = bufB + BUFB;           // tile kt+2 (prefetch target)

    // ---- prefetch KV tiles 0,1 ----
    {
        size_t base0 = ((size_t)btrow[0] * NKVH + kvh) * (size_t)(BK * HD);
        load_kv_tile(bufA, base0, tid);
        CP_COMMIT();
        if (n_tiles > 1) {
            size_t base1 = ((size_t)btrow[1] * NKVH + kvh) * (size_t)(BK * HD);
            load_kv_tile(bufB, base1, tid);
        }
        CP_COMMIT();
    }

    // ---- load fp32 Q tile, scale+convert to f16, store to smem ----
    {
        const float s = 0.12753102f;   // (1/sqrt(128)) * log2(e)
        #pragma unroll
        for (int j = 0; j < 8; ++j) {
            int c = tid + j * NTHR;
            int row = c >> 4, cb = c & 15;
            const float* src = qf + ((size_t)(q_start + q0 + row) * NH + head) * HD + cb * 8;
            float4 a = *reinterpret_cast<const float4*>(src);
            float4 b = *reinterpret_cast<const float4*>(src + 4);
            uint4 u;
            __half2 h;
            h = __floats2half2_rn(a.x * s, a.y * s); u.x = *reinterpret_cast<uint32_t*>(&h);
            h = __floats2half2_rn(a.z * s, a.w * s); u.y = *reinterpret_cast<uint32_t*>(&h);
            h = __floats2half2_rn(b.x * s, b.y * s); u.z = *reinterpret_cast<uint32_t*>(&h);
            h = __floats2half2_rn(b.z * s, b.w * s); u.w = *reinterpret_cast<uint32_t*>(&h);
            *reinterpret_cast<uint4*>(smem + SM_Q + swz(row, cb)) = u;
        }
    }
    CP_WAIT1();          // tile 0 arrived (tile 1 may still fly)
    __syncthreads();     // Q stores + tile 0 visible
    uint32_t aQ[8][4];
    #pragma unroll
    for (int kf = 0; kf < 8; ++kf)
        ldsm4(sb + SM_Q + swz(16 * w + rA, 2 * kf + cA), aQ[kf]);

    float O[16][4];
    #pragma unroll
    for (int nd = 0; nd < 16; ++nd)
        #pragma unroll
        for (int i = 0; i < 4; ++i) O[nd][i] = 0.f;
    float ls0 = 0.f, ls1 = 0.f, m0 = 0.f, m1 = 0.f;

    float S[8][4];
    qk_tile(S, aQ, bufA, rB, cB);    // scores of tile 0

    // ---- main loop: wait/prefetch -> softmax(kt) -> QK(kt+1) -> PV(kt) -> ls ----
    for (int kt = 0; kt < n_tiles - 1; ++kt) {
        // tile kt+1 resident+visible; all warps done reading tile kt-1
        CP_WAIT0();
        __syncthreads();
        const int nt = kt + 2;
        if (nt < n_tiles) {
            size_t base = ((size_t)btrow[nt] * NKVH + kvh) * (size_t)(BK * HD);
            load_kv_tile(bufC, base, tid);
        }
        CP_COMMIT();   // possibly-empty commit keeps group counting fixed

        // -- softmax on S (tile kt) --
        if (kt == 0) {
            float mx0 = -1e30f, mx1 = -1e30f;
            #pragma unroll
            for (int nf = 0; nf < 8; ++nf) {
                mx0 = fmaxf(mx0, fmaxf(S[nf][0], S[nf][1]));
                mx1 = fmaxf(mx1, fmaxf(S[nf][2], S[nf][3]));
            }
            mx0 = fmaxf(mx0, __shfl_xor_sync(0xffffffffu, mx0, 1));
            mx0 = fmaxf(mx0, __shfl_xor_sync(0xffffffffu, mx0, 2));
            mx1 = fmaxf(mx1, __shfl_xor_sync(0xffffffffu, mx1, 1));
            mx1 = fmaxf(mx1, __shfl_xor_sync(0xffffffffu, mx1, 2));
            m0 = mx0; m1 = mx1;
        }
        const int kb = kt * BK;
        if (kb + BK - 1 > qpos_min) {
            #pragma unroll
            for (int nf = 0; nf < 8; ++nf) {
                const int kp = kb + 8 * nf + 2 * t;
                S[nf][0] = (kp     <= qpos0) ? S[nf][0] - m0 : -100.f;
                S[nf][1] = (kp + 1 <= qpos0) ? S[nf][1] - m0 : -100.f;
                S[nf][2] = (kp     <= qpos1) ? S[nf][2] - m1 : -100.f;
                S[nf][3] = (kp + 1 <= qpos1) ? S[nf][3] - m1 : -100.f;
            }
        } else {
            #pragma unroll
            for (int nf = 0; nf < 8; ++nf) {
                S[nf][0] -= m0; S[nf][1] -= m0;
                S[nf][2] -= m1; S[nf][3] -= m1;
            }
        }
        uint32_t aP[4][4];
        #pragma unroll
        for (int kf = 0; kf < 4; ++kf) {
            __half2 h;
            h = h2exp2(__floats2half2_rn(S[2*kf][0],   S[2*kf][1]));   aP[kf][0] = *reinterpret_cast<uint32_t*>(&h);
            h = h2exp2(__floats2half2_rn(S[2*kf][2],   S[2*kf][3]));   aP[kf][1] = *reinterpret_cast<uint32_t*>(&h);
            h = h2exp2(__floats2half2_rn(S[2*kf+1][0], S[2*kf+1][1])); aP[kf][2] = *reinterpret_cast<uint32_t*>(&h);
            h = h2exp2(__floats2half2_rn(S[2*kf+1][2], S[2*kf+1][3])); aP[kf][3] = *reinterpret_cast<uint32_t*>(&h);
        }

        // -- QK(kt+1) then PV(kt); independent blocks, ptxas interleaves --
        qk_tile(S, aQ, bufB, rB, cB);
        pv_tile(O, aP, bufA, rA, cA);

        // -- ls sums (moved off the softmax->MMA critical path; same f16 values) --
        #pragma unroll
        for (int kf = 0; kf < 4; ++kf) {
            const __half2 p00 = *reinterpret_cast<const __half2*>(&aP[kf][0]);
            const __half2 p01 = *reinterpret_cast<const __half2*>(&aP[kf][1]);
            const __half2 p10 = *reinterpret_cast<const __half2*>(&aP[kf][2]);
            const __half2 p11 = *reinterpret_cast<const __half2*>(&aP[kf][3]);
            ls0 += __low2float(p00) + __high2float(p00) + __low2float(p10) + __high2float(p10);
            ls1 += __low2float(p01) + __high2float(p01) + __low2float(p11) + __high2float(p11);
        }

        // rotate ring
        uint32_t tmp = bufA; bufA = bufB; bufB = bufC; bufC = tmp;
    }

    // ---- tail tile (diagonal): warp w only needs kf-groups 0..w ----
    {
        const int kt = n_tiles - 1;
        if (kt == 0) {
            float mx0 = -1e30f, mx1 = -1e30f;
            #pragma unroll
            for (int nf = 0; nf < 8; ++nf) {
                mx0 = fmaxf(mx0, fmaxf(S[nf][0], S[nf][1]));
                mx1 = fmaxf(mx1, fmaxf(S[nf][2], S[nf][3]));
            }
            mx0 = fmaxf(mx0, __shfl_xor_sync(0xffffffffu, mx0, 1));
            mx0 = fmaxf(mx0, __shfl_xor_sync(0xffffffffu, mx0, 2));
            mx1 = fmaxf(mx1, __shfl_xor_sync(0xffffffffu, mx1, 1));
            mx1 = fmaxf(mx1, __shfl_xor_sync(0xffffffffu, mx1, 2));
            m0 = mx0; m1 = mx1;
        }
        const int kb = kt * BK;
        #pragma unroll
        for (int nf = 0; nf < 8; ++nf) {
            const int kp = kb + 8 * nf + 2 * t;
            S[nf][0] = (kp     <= qpos0) ? S[nf][0] - m0 : -100.f;
            S[nf][1] = (kp + 1 <= qpos0) ? S[nf][1] - m0 : -100.f;
            S[nf][2] = (kp     <= qpos1) ? S[nf][2] - m1 : -100.f;
            S[nf][3] = (kp + 1 <= qpos1) ? S[nf][3] - m1 : -100.f;
        }
        #pragma unroll
        for (int kf = 0; kf < 4; ++kf) {
            if (kf > w) break;            // keys kb+16kf.. all-masked for this warp
            uint32_t aPk[4];
            __half2 h;
            h = h2exp2(__floats2half2_rn(S[2*kf][0],   S[2*kf][1]));   aPk[0] = *reinterpret_cast<uint32_t*>(&h);
            h = h2exp2(__floats2half2_rn(S[2*kf][2],   S[2*kf][3]));   aPk[1] = *reinterpret_cast<uint32_t*>(&h);
            h = h2exp2(__floats2half2_rn(S[2*kf+1][0], S[2*kf+1][1])); aPk[2] = *reinterpret_cast<uint32_t*>(&h);
            h = h2exp2(__floats2half2_rn(S[2*kf+1][2], S[2*kf+1][3])); aPk[3] = *reinterpret_cast<uint32_t*>(&h);
            const __half2 p00 = *reinterpret_cast<const __half2*>(&aPk[0]);
            const __half2 p01 = *reinterpret_cast<const __half2*>(&aPk[1]);
            const __half2 p10 = *reinterpret_cast<const __half2*>(&aPk[2]);
            const __half2 p11 = *reinterpret_cast<const __half2*>(&aPk[3]);
            ls0 += __low2float(p00) + __high2float(p00) + __low2float(p10) + __high2float(p10);
            ls1 += __low2float(p01) + __high2float(p01) + __low2float(p11) + __high2float(p11);
            #pragma unroll
            for (int ndp = 0; ndp < 8; ++ndp) {
                uint32_t vv[4];
                ldsm4t(bufA + OFF_V + swz(16 * kf + rA, 2 * ndp + cA), vv);
                mma_f16(O[2*ndp],     aPk, vv);
                mma_f16(O[2*ndp + 1], aPk, vv + 2);
            }
        }
    }

    // ---- epilogue ----
    ls0 += __shfl_xor_sync(0xffffffffu, ls0, 1);
    ls0 += __shfl_xor_sync(0xffffffffu, ls0, 2);
    ls1 += __shfl_xor_sync(0xffffffffu, ls1, 1);
    ls1 += __shfl_xor_sync(0xffffffffu, ls1, 2);
    const float inv0 = 1.0f / ls0, inv1 = 1.0f / ls1;

    const int row0 = q_start + q0 + 16 * w + g;
    float* o0 = out + ((size_t)row0 * NH + head) * HD;
    float* o1 = o0 + (size_t)8 * NH * HD;
    #pragma unroll
    for (int nd = 0; nd < 16; ++nd) {
        float2 u0 = make_float2(O[nd][0] * inv0, O[nd][1] * inv0);
        float2 u1 = make_float2(O[nd][2] * inv1, O[nd][3] * inv1);
        *reinterpret_cast<float2*>(o0 + 8 * nd + 2 * t) = u0;
        *reinterpret_cast<float2*>(o1 + 8 * nd + 2 * t) = u1;
    }
}

extern "C" void kernel_launch(void* const* d_in, const int* in_sizes, int n_in,
                              void* d_out, int out_size)
{
    const float* q   = (const float*)d_in[0];
    const float* kc  = (const float*)d_in[1];
    const float* vc  = (const float*)d_in[2];
    const int*   cuq = (const int*)d_in[3];
    const int*   cuk = (const int*)d_in[4];
    const int*   bt  = (const int*)d_in[5];
    float*       out = (float*)d_out;

    const int tot_q      = in_sizes[0] / (NH * HD);          // 2048
    const int nseq       = in_sizes[3] - 1;                  // 2
    const int lq         = tot_q / nseq;                     // 1024
    const int max_blocks = in_sizes[5] / nseq;               // 32
    const int nblk_tot   = in_sizes[1] / (BK * NKVH * HD);   // 64
    const int q_tiles    = (lq + BQ - 1) / BQ;               // 16

    prep_kv<<<nblk_tot * NKVH * 2, 256>>>(kc, vc);

    cudaFuncSetAttribute(attn_main, cudaFuncAttributeMaxDynamicSharedMemorySize, SMEM_BYTES);
    dim3 grid(q_tiles, NH, nseq);
    attn_main<<<grid, NTHR, SMEM_BYTES>>>(q, cuq, cuk, bt, out, max_blocks);
}